// round 11
// baseline (speedup 1.0000x reference)
#include <cuda_runtime.h>
#include <cstdint>

// Problem constants (fixed by dataset)
#define BATCH   4
#define DIN     4096
#define DOUT    11008
#define RANK    512

// k1/k2 low-rank tiling
#define NCHUNK  256
#define CHUNK_D 16                 // d-rows per chunk

// k_gemv streaming
#define KH      2048               // K per CTA (K-split by 2)
#define KT      128                // floats per stage per row
#define NSTAGE  (KH / KT)          // 16
#define DEPTH   4                  // CTA-wide ring stages (16 KB each)

// Scratch (allocation-free rule: __device__ globals)
__device__ float  g_xm[BATCH * DIN];            // masked input, SoA [b][d]
__device__ float4 g_lr_part[NCHUNK * 512];      // low-rank partials (2 MB)
__device__ float  g_lrs[BATCH * RANK];          // S-scaled lr, SoA [b][r]
__device__ float  g_part[2][BATCH * DOUT];      // per-K-half GEMV partials

// packed f32x2 FMA: acc.{lo,hi} += a.{lo,hi} * b.{lo,hi}
#define FMA2(acc, a, b) \
    asm volatile("fma.rn.f32x2 %0, %1, %2, %0;" : "+l"(acc) : "l"(a), "l"(b))

__device__ __forceinline__ void cp_async16(void* s, const void* g) {
    uint32_t sa = (uint32_t)__cvta_generic_to_shared(s);
    asm volatile("cp.async.cg.shared.global [%0], [%1], 16;\n" :: "r"(sa), "l"(g));
}
#define CP_COMMIT()  asm volatile("cp.async.commit_group;\n" ::: "memory")
#define CP_WAIT(n)   asm volatile("cp.async.wait_group %0;\n" :: "n"(n) : "memory")

// ---------------------------------------------------------------------------
// Kernel 1: mask split + per-chunk low-rank partial   (grid 256 x 128)
// ---------------------------------------------------------------------------
__global__ __launch_bounds__(128) void k_mask_lr(
    const float* __restrict__ input,
    const float* __restrict__ V,
    const float* __restrict__ scale,
    const float* __restrict__ thr)
{
    __shared__ float4 sxc[CHUNK_D];

    const int c = blockIdx.x;
    const int t = threadIdx.x;

    if (t < CHUNK_D) {
        const int d = c * CHUNK_D + t;
        const float th = thr[0];
        const float sc = scale[d];
        float x0 = input[0 * DIN + d];
        float x1 = input[1 * DIN + d];
        float x2 = input[2 * DIN + d];
        float x3 = input[3 * DIN + d];
        bool m0 = fabsf(x0 * sc) > th;
        bool m1 = fabsf(x1 * sc) > th;
        bool m2 = fabsf(x2 * sc) > th;
        bool m3 = fabsf(x3 * sc) > th;
        g_xm[0 * DIN + d] = m0 ? x0 : 0.0f;
        g_xm[1 * DIN + d] = m1 ? x1 : 0.0f;
        g_xm[2 * DIN + d] = m2 ? x2 : 0.0f;
        g_xm[3 * DIN + d] = m3 ? x3 : 0.0f;
        float4 xc;
        xc.x = m0 ? 0.0f : x0;
        xc.y = m1 ? 0.0f : x1;
        xc.z = m2 ? 0.0f : x2;
        xc.w = m3 ? 0.0f : x3;
        sxc[t] = xc;
    }
    __syncthreads();

    const float4* __restrict__ V4 = reinterpret_cast<const float4*>(V);

    float4 v[CHUNK_D];                       // 16 LDG.128 in flight
#pragma unroll
    for (int j = 0; j < CHUNK_D; j++)
        v[j] = V4[(size_t)(c * CHUNK_D + j) * (RANK / 4) + t];

    float4 a0 = make_float4(0.f, 0.f, 0.f, 0.f);
    float4 a1 = a0, a2 = a0, a3 = a0;
#pragma unroll
    for (int j = 0; j < CHUNK_D; j++) {
        const float4 xb = sxc[j];
        a0.x += v[j].x * xb.x; a0.y += v[j].x * xb.y; a0.z += v[j].x * xb.z; a0.w += v[j].x * xb.w;
        a1.x += v[j].y * xb.x; a1.y += v[j].y * xb.y; a1.z += v[j].y * xb.z; a1.w += v[j].y * xb.w;
        a2.x += v[j].z * xb.x; a2.y += v[j].z * xb.y; a2.z += v[j].z * xb.z; a2.w += v[j].z * xb.w;
        a3.x += v[j].w * xb.x; a3.y += v[j].w * xb.y; a3.z += v[j].w * xb.z; a3.w += v[j].w * xb.w;
    }

    float4* outp = g_lr_part + (size_t)c * 512;   // coalesced stores (permuted r)
    outp[0 * 128 + t] = a0;
    outp[1 * 128 + t] = a1;
    outp[2 * 128 + t] = a2;
    outp[3 * 128 + t] = a3;
}

// ---------------------------------------------------------------------------
// Kernel 2: reduce partials over 256 chunks, fold S   (grid 16 x 256)
//   Element e (permuted r): r = 4*(e&127) + (e>>7).
// ---------------------------------------------------------------------------
__global__ __launch_bounds__(256) void k_lr_reduce(const float* __restrict__ S)
{
    __shared__ float4 sred[256];

    const int tid   = threadIdx.x;
    const int eloc  = tid & 31;
    const int clane = tid >> 5;                 // chunk lane [0,8)
    const int e     = blockIdx.x * 32 + eloc;

    float4 acc = make_float4(0.f, 0.f, 0.f, 0.f);
#pragma unroll 8
    for (int j = 0; j < NCHUNK / 8; j++) {
        float4 p = g_lr_part[(size_t)(clane + 8 * j) * 512 + e];  // coalesced over e
        acc.x += p.x; acc.y += p.y; acc.z += p.z; acc.w += p.w;
    }
    sred[tid] = acc;
    __syncthreads();

    if (tid < 32) {
        float4 a = sred[tid];
#pragma unroll
        for (int l = 1; l < 8; l++) {
            float4 p = sred[tid + 32 * l];
            a.x += p.x; a.y += p.y; a.z += p.z; a.w += p.w;
        }
        const int ee = blockIdx.x * 32 + tid;
        const int r  = 4 * (ee & 127) + (ee >> 7);
        const float s = S[r];
        g_lrs[0 * RANK + r] = a.x * s;
        g_lrs[1 * RANK + r] = a.y * s;
        g_lrs[2 * RANK + r] = a.z * s;
        g_lrs[3 * RANK + r] = a.w * s;
    }
}

// ---------------------------------------------------------------------------
// Kernel 3: streaming GEMV partial — CTA-WIDE cp.async ring.
//   grid 296 = 148 row-ranges x 2 K-halves; 256 thr, 8 warps x 4 rows.
//   Stage = 32 rows x 128 floats (16 KB); DEPTH 4; loads guarded per valid
//   row so short row-chunks cost bytes-proportional time (fixes the ~22%
//   structural imbalance of per-warp rings).
//   Pipeline per stage: wait(DEPTH-2) -> sync -> compute(s) -> sync ->
//   issue(s+DEPTH-1) -> commit (always-commit keeps wait semantics uniform).
// ---------------------------------------------------------------------------
__global__ __launch_bounds__(256, 2) void k_gemv(
    const float* __restrict__ W,
    const float* __restrict__ U)
{
    extern __shared__ float smem[];
    float* sx   = smem;            // 8192 floats: x-half SoA [b][2048]
    float* slr  = smem + 8192;     // 1024 floats: lr-half SoA [b][256]
    float* ring = smem + 9216;     // DEPTH * 4096 floats (64 KB)

    const int tid  = threadIdx.x;
    const int wid  = tid >> 5;
    const int lane = tid & 31;
    const int pair = blockIdx.x >> 1;
    const int kh   = blockIdx.x & 1;
    const int row0  = 74 * pair + (pair < 56 ? pair : 56);
    const int nrows = (pair < 56) ? 75 : 74;

    // ---- fill x-half + lr-half via cp.async ----
    {
        const float4* gx4 = reinterpret_cast<const float4*>(g_xm);
        float4*       sx4 = reinterpret_cast<float4*>(sx);
#pragma unroll
        for (int i = 0; i < 8; i++) {
            const int i2 = tid + 256 * i;         // [0,2048)
            const int b = i2 >> 9, dd = i2 & 511;
            cp_async16(&sx4[i2], &gx4[b * 1024 + kh * 512 + dd]);
        }
        const float4* gl4 = reinterpret_cast<const float4*>(g_lrs);
        float4*       sl4 = reinterpret_cast<float4*>(slr);
        {
            const int b = tid >> 6, rr = tid & 63;
            cp_async16(&sl4[tid], &gl4[b * 128 + kh * 64 + rr]);
        }
        CP_COMMIT();
        CP_WAIT(0);
    }
    __syncthreads();

    const float* wbase = W + (size_t)row0 * DIN + kh * KH;

    for (int c = 0; c < 3; c++) {
        const int crow0 = c * 32;                 // chunk base row (CTA-local)

        // stage loader: thread tid covers 4 of 1024 16B-chunks, stride 256.
        // chunk_id: row = id>>5, off = (id&31)*4 floats. Guarded per row.
        auto issue_stage = [&](int s) {
#pragma unroll
            for (int j = 0; j < 4; j++) {
                const int id  = tid + 256 * j;
                const int row = id >> 5;
                const int off = (id & 31) * 4;
                if (crow0 + row < nrows)
                    cp_async16(ring + (s % DEPTH) * 4096 + row * 128 + off,
                               wbase + (size_t)(crow0 + row) * DIN + s * KT + off);
            }
        };

        // prologue: stages 0..DEPTH-2
#pragma unroll
        for (int s = 0; s < DEPTH - 1; s++) {
            issue_stage(s);
            CP_COMMIT();
        }

        unsigned long long acc2[4][4];
#pragma unroll
        for (int r = 0; r < 4; r++)
#pragma unroll
            for (int b = 0; b < 4; b++) acc2[r][b] = 0ULL;

        bool valid[4];
#pragma unroll
        for (int r = 0; r < 4; r++)
            valid[r] = (crow0 + wid * 4 + r) < nrows;

#pragma unroll
        for (int s = 0; s < NSTAGE; s++) {
            CP_WAIT(DEPTH - 2);                   // stage s resident
            __syncthreads();

            const float* buf = ring + (s % DEPTH) * 4096;
            ulonglong2 wv[4], xv[4];
#pragma unroll
            for (int r = 0; r < 4; r++)
                wv[r] = *reinterpret_cast<const ulonglong2*>(buf + (wid * 4 + r) * 128 + lane * 4);
#pragma unroll
            for (int b = 0; b < 4; b++)
                xv[b] = *reinterpret_cast<const ulonglong2*>(sx + b * 2048 + s * KT + lane * 4);
#pragma unroll
            for (int r = 0; r < 4; r++)
                if (valid[r]) {
#pragma unroll
                    for (int b = 0; b < 4; b++) {
                        FMA2(acc2[r][b], wv[r].x, xv[b].x);
                        FMA2(acc2[r][b], wv[r].y, xv[b].y);
                    }
                }

            __syncthreads();                      // all warps done with slot
            const int tnext = s + (DEPTH - 1);
            if (tnext < NSTAGE) issue_stage(tnext);
            CP_COMMIT();                          // always-commit
        }

        // U epilogue on this K-half's 256 ranks
#pragma unroll
        for (int r = 0; r < 4; r++) {
            if (!valid[r]) continue;
            const float* up = U + (size_t)(row0 + crow0 + wid * 4 + r) * RANK + kh * 256;
#pragma unroll
            for (int q = 0; q < 2; q++) {
                const ulonglong2 uv = *reinterpret_cast<const ulonglong2*>(up + q * 128 + lane * 4);
#pragma unroll
                for (int b = 0; b < 4; b++) {
                    const ulonglong2 lv =
                        *reinterpret_cast<const ulonglong2*>(slr + b * 256 + q * 128 + lane * 4);
                    FMA2(acc2[r][b], uv.x, lv.x);
                    FMA2(acc2[r][b], uv.y, lv.y);
                }
            }
        }

        // fold packed halves, warp-reduce, write partial
#pragma unroll
        for (int r = 0; r < 4; r++) {
            if (!valid[r]) continue;
#pragma unroll
            for (int b = 0; b < 4; b++) {
                float v = __uint_as_float((uint32_t)acc2[r][b])
                        + __uint_as_float((uint32_t)(acc2[r][b] >> 32));
                v += __shfl_xor_sync(0xffffffffu, v, 16);
                v += __shfl_xor_sync(0xffffffffu, v, 8);
                v += __shfl_xor_sync(0xffffffffu, v, 4);
                v += __shfl_xor_sync(0xffffffffu, v, 2);
                v += __shfl_xor_sync(0xffffffffu, v, 1);
                if (lane == 0)
                    g_part[kh][b * DOUT + row0 + crow0 + wid * 4 + r] = v;
            }
        }
    }
}

// ---------------------------------------------------------------------------
// Kernel 4: out = part0 + part1 + bias   (grid 43 x 256, float4)
// ---------------------------------------------------------------------------
__global__ __launch_bounds__(256) void k_add(
    const float* __restrict__ bias,
    float* __restrict__ out)
{
    const int e = blockIdx.x * 256 + threadIdx.x;      // [0, 11008) float4 units
    const float4 a = reinterpret_cast<const float4*>(g_part[0])[e];
    const float4 b = reinterpret_cast<const float4*>(g_part[1])[e];
    const int o4 = e % (DOUT / 4);
    const float4 bs = reinterpret_cast<const float4*>(bias)[o4];
    float4 o;
    o.x = a.x + b.x + bs.x;
    o.y = a.y + b.y + bs.y;
    o.z = a.z + b.z + bs.z;
    o.w = a.w + b.w + bs.w;
    reinterpret_cast<float4*>(out)[e] = o;
}

// ---------------------------------------------------------------------------
extern "C" void kernel_launch(void* const* d_in, const int* in_sizes, int n_in,
                              void* d_out, int out_size)
{
    const float* input  = (const float*)d_in[0];
    const float* weight = (const float*)d_in[1];
    const float* bias   = (const float*)d_in[2];
    const float* U      = (const float*)d_in[3];
    const float* S      = (const float*)d_in[4];
    const float* V      = (const float*)d_in[5];
    const float* scale  = (const float*)d_in[6];
    const float* thresh = (const float*)d_in[7];
    float* out = (float*)d_out;

    const int smem_bytes = (8192 + 1024 + DEPTH * 4096) * (int)sizeof(float); // 102400
    cudaFuncSetAttribute(k_gemv, cudaFuncAttributeMaxDynamicSharedMemorySize, smem_bytes);

    k_mask_lr<<<NCHUNK, 128>>>(input, V, scale, thresh);
    k_lr_reduce<<<16, 256>>>(S);
    k_gemv<<<296, 256, smem_bytes>>>(weight, U);
    k_add<<<43, 256>>>(bias, out);
}

// round 12
// speedup vs baseline: 1.1138x; 1.1138x over previous
#include <cuda_runtime.h>
#include <cstdint>

// Problem constants (fixed by dataset)
#define BATCH   4
#define DIN     4096
#define DOUT    11008
#define RANK    512

// k1/k2 low-rank tiling
#define NCHUNK  256
#define CHUNK_D 16                 // d-rows per chunk

// k_gemv streaming
#define KH      2048               // K per CTA (K-split by 2)
#define KT      128                // floats per stage per row
#define NSTAGE  (KH / KT)          // 16
#define DEPTH   4                  // per-warp ring stages (3 groups in flight)

// Scratch (allocation-free rule: __device__ globals)
__device__ float  g_xm[BATCH * DIN];            // masked input, SoA [b][d]
__device__ float4 g_lr_part[NCHUNK * 512];      // low-rank partials (2 MB)
__device__ float  g_lrs[BATCH * RANK];          // S-scaled lr, SoA [b][r]
__device__ float  g_part[2][BATCH * DOUT];      // per-K-half GEMV partials

// packed f32x2 FMA: acc.{lo,hi} += a.{lo,hi} * b.{lo,hi}
#define FMA2(acc, a, b) \
    asm volatile("fma.rn.f32x2 %0, %1, %2, %0;" : "+l"(acc) : "l"(a), "l"(b))

__device__ __forceinline__ void cp_async16(void* s, const void* g) {
    uint32_t sa = (uint32_t)__cvta_generic_to_shared(s);
    asm volatile("cp.async.cg.shared.global [%0], [%1], 16;\n" :: "r"(sa), "l"(g));
}
#define CP_COMMIT()  asm volatile("cp.async.commit_group;\n" ::: "memory")
#define CP_WAIT(n)   asm volatile("cp.async.wait_group %0;\n" :: "n"(n) : "memory")

// ---------------------------------------------------------------------------
// Kernel 1: mask split + per-chunk low-rank partial   (grid 256 x 128)
//   Partials stored coalesced in permuted layout: slot = c*512 + comp*128 + t.
// ---------------------------------------------------------------------------
__global__ __launch_bounds__(128) void k_mask_lr(
    const float* __restrict__ input,
    const float* __restrict__ V,
    const float* __restrict__ scale,
    const float* __restrict__ thr)
{
    __shared__ float4 sxc[CHUNK_D];

    const int c = blockIdx.x;
    const int t = threadIdx.x;

    if (t < CHUNK_D) {
        const int d = c * CHUNK_D + t;
        const float th = thr[0];
        const float sc = scale[d];
        float x0 = input[0 * DIN + d];
        float x1 = input[1 * DIN + d];
        float x2 = input[2 * DIN + d];
        float x3 = input[3 * DIN + d];
        bool m0 = fabsf(x0 * sc) > th;
        bool m1 = fabsf(x1 * sc) > th;
        bool m2 = fabsf(x2 * sc) > th;
        bool m3 = fabsf(x3 * sc) > th;
        g_xm[0 * DIN + d] = m0 ? x0 : 0.0f;
        g_xm[1 * DIN + d] = m1 ? x1 : 0.0f;
        g_xm[2 * DIN + d] = m2 ? x2 : 0.0f;
        g_xm[3 * DIN + d] = m3 ? x3 : 0.0f;
        float4 xc;
        xc.x = m0 ? 0.0f : x0;
        xc.y = m1 ? 0.0f : x1;
        xc.z = m2 ? 0.0f : x2;
        xc.w = m3 ? 0.0f : x3;
        sxc[t] = xc;
    }
    __syncthreads();

    const float4* __restrict__ V4 = reinterpret_cast<const float4*>(V);

    float4 v[CHUNK_D];                       // 16 LDG.128 in flight
#pragma unroll
    for (int j = 0; j < CHUNK_D; j++)
        v[j] = V4[(size_t)(c * CHUNK_D + j) * (RANK / 4) + t];

    float4 a0 = make_float4(0.f, 0.f, 0.f, 0.f);
    float4 a1 = a0, a2 = a0, a3 = a0;
#pragma unroll
    for (int j = 0; j < CHUNK_D; j++) {
        const float4 xb = sxc[j];
        a0.x += v[j].x * xb.x; a0.y += v[j].x * xb.y; a0.z += v[j].x * xb.z; a0.w += v[j].x * xb.w;
        a1.x += v[j].y * xb.x; a1.y += v[j].y * xb.y; a1.z += v[j].y * xb.z; a1.w += v[j].y * xb.w;
        a2.x += v[j].z * xb.x; a2.y += v[j].z * xb.y; a2.z += v[j].z * xb.z; a2.w += v[j].z * xb.w;
        a3.x += v[j].w * xb.x; a3.y += v[j].w * xb.y; a3.z += v[j].w * xb.z; a3.w += v[j].w * xb.w;
    }

    float4* outp = g_lr_part + (size_t)c * 512;   // coalesced stores (permuted r)
    outp[0 * 128 + t] = a0;
    outp[1 * 128 + t] = a1;
    outp[2 * 128 + t] = a2;
    outp[3 * 128 + t] = a3;
}

// ---------------------------------------------------------------------------
// Kernel 2: reduce partials over 256 chunks, fold S   (grid 16 x 256)
//   Element e (permuted r): r = 4*(e&127) + (e>>7).
// ---------------------------------------------------------------------------
__global__ __launch_bounds__(256) void k_lr_reduce(const float* __restrict__ S)
{
    __shared__ float4 sred[256];

    const int tid   = threadIdx.x;
    const int eloc  = tid & 31;
    const int clane = tid >> 5;                 // chunk lane [0,8)
    const int e     = blockIdx.x * 32 + eloc;

    float4 acc = make_float4(0.f, 0.f, 0.f, 0.f);
#pragma unroll 8
    for (int j = 0; j < NCHUNK / 8; j++) {
        float4 p = g_lr_part[(size_t)(clane + 8 * j) * 512 + e];  // coalesced over e
        acc.x += p.x; acc.y += p.y; acc.z += p.z; acc.w += p.w;
    }
    sred[tid] = acc;
    __syncthreads();

    if (tid < 32) {
        float4 a = sred[tid];
#pragma unroll
        for (int l = 1; l < 8; l++) {
            float4 p = sred[tid + 32 * l];
            a.x += p.x; a.y += p.y; a.z += p.z; a.w += p.w;
        }
        const int ee = blockIdx.x * 32 + tid;
        const int r  = 4 * (ee & 127) + (ee >> 7);
        const float s = S[r];
        g_lrs[0 * RANK + r] = a.x * s;
        g_lrs[1 * RANK + r] = a.y * s;
        g_lrs[2 * RANK + r] = a.z * s;
        g_lrs[3 * RANK + r] = a.w * s;
    }
}

// ---------------------------------------------------------------------------
// Kernel 3: streaming GEMV partial — per-warp cp.async ring (barrier-free
//   mainloop) + STRIDE-8 ROW INTERLEAVE for warp load balance.
//   grid 296 = 148 row-ranges x 2 K-halves; 256 thr, 8 warps.
//   Warp w, group g, slot r handles CTA-local row  idx = w + 32g + 8r
//   -> the 10-11 row tail spreads across ALL 8 warps (2,2,2,1,1,1,1,1)
//   instead of 3 warps + 5 idle, keeping every warp's stream live.
// ---------------------------------------------------------------------------
__global__ __launch_bounds__(256, 2) void k_gemv(
    const float* __restrict__ W,
    const float* __restrict__ U)
{
    extern __shared__ float smem[];
    float* sx   = smem;            // 8192 floats: x-half SoA [b][2048]
    float* slr  = smem + 8192;     // 1024 floats: lr-half SoA [b][256]
    float* ring = smem + 9216;     // 8 warps * DEPTH * 512 floats (64 KB)

    const int tid  = threadIdx.x;
    const int wid  = tid >> 5;
    const int lane = tid & 31;
    const int pair = blockIdx.x >> 1;
    const int kh   = blockIdx.x & 1;
    const int row0  = 74 * pair + (pair < 56 ? pair : 56);
    const int nrows = (pair < 56) ? 75 : 74;

    // ---- fill x-half + lr-half via cp.async ----
    {
        const float4* gx4 = reinterpret_cast<const float4*>(g_xm);
        float4*       sx4 = reinterpret_cast<float4*>(sx);
#pragma unroll
        for (int i = 0; i < 8; i++) {
            const int i2 = tid + 256 * i;         // [0,2048)
            const int b = i2 >> 9, dd = i2 & 511;
            cp_async16(&sx4[i2], &gx4[b * 1024 + kh * 512 + dd]);
        }
        const float4* gl4 = reinterpret_cast<const float4*>(g_lrs);
        float4*       sl4 = reinterpret_cast<float4*>(slr);
        {
            const int b = tid >> 6, rr = tid & 63;
            cp_async16(&sl4[tid], &gl4[b * 128 + kh * 64 + rr]);
        }
        CP_COMMIT();
        CP_WAIT(0);
    }
    __syncthreads();

    float* wring = ring + wid * (DEPTH * 512);

    for (int g = 0; g < 3; g++) {
        // stride-8 interleaved CTA-local rows for this warp/group
        int  idx[4]; bool valid[4]; const float* wp[4];
        bool any = false;
#pragma unroll
        for (int r = 0; r < 4; r++) {
            idx[r]   = wid + 32 * g + 8 * r;
            valid[r] = idx[r] < nrows;
            any     |= valid[r];
            wp[r]    = W + (size_t)(row0 + idx[r]) * DIN + kh * KH;
        }
        if (!any) continue;                       // warp-local skip; no barriers

        // prologue: stages 0..DEPTH-2
#pragma unroll
        for (int s = 0; s < DEPTH - 1; s++) {
#pragma unroll
            for (int r = 0; r < 4; r++)
                if (valid[r])
                    cp_async16(wring + (s % DEPTH) * 512 + r * 128 + lane * 4,
                               wp[r] + s * KT + lane * 4);
            CP_COMMIT();
        }

        unsigned long long acc2[4][4];
#pragma unroll
        for (int r = 0; r < 4; r++)
#pragma unroll
            for (int b = 0; b < 4; b++) acc2[r][b] = 0ULL;

        // mainloop: always-commit keeps wait_group(DEPTH-1) meaning uniform
#pragma unroll
        for (int s = 0; s < NSTAGE; s++) {
            const int tnext = s + (DEPTH - 1);
            if (tnext < NSTAGE) {
#pragma unroll
                for (int r = 0; r < 4; r++)
                    if (valid[r])
                        cp_async16(wring + (tnext % DEPTH) * 512 + r * 128 + lane * 4,
                                   wp[r] + tnext * KT + lane * 4);
            }
            CP_COMMIT();
            CP_WAIT(DEPTH - 1);

            const float* buf = wring + (s % DEPTH) * 512;
            ulonglong2 wv[4], xv[4];
#pragma unroll
            for (int r = 0; r < 4; r++)
                wv[r] = *reinterpret_cast<const ulonglong2*>(buf + r * 128 + lane * 4);
#pragma unroll
            for (int b = 0; b < 4; b++)
                xv[b] = *reinterpret_cast<const ulonglong2*>(sx + b * 2048 + s * KT + lane * 4);
#pragma unroll
            for (int r = 0; r < 4; r++)
#pragma unroll
                for (int b = 0; b < 4; b++) {
                    FMA2(acc2[r][b], wv[r].x, xv[b].x);
                    FMA2(acc2[r][b], wv[r].y, xv[b].y);
                }
        }

        // U epilogue on this K-half's 256 ranks
#pragma unroll
        for (int r = 0; r < 4; r++) {
            if (!valid[r]) continue;
            const float* up = U + (size_t)(row0 + idx[r]) * RANK + kh * 256;
#pragma unroll
            for (int q = 0; q < 2; q++) {
                const ulonglong2 uv = *reinterpret_cast<const ulonglong2*>(up + q * 128 + lane * 4);
#pragma unroll
                for (int b = 0; b < 4; b++) {
                    const ulonglong2 lv =
                        *reinterpret_cast<const ulonglong2*>(slr + b * 256 + q * 128 + lane * 4);
                    FMA2(acc2[r][b], uv.x, lv.x);
                    FMA2(acc2[r][b], uv.y, lv.y);
                }
            }
        }

        // fold packed halves, warp-reduce, write partial
#pragma unroll
        for (int r = 0; r < 4; r++) {
            if (!valid[r]) continue;
#pragma unroll
            for (int b = 0; b < 4; b++) {
                float v = __uint_as_float((uint32_t)acc2[r][b])
                        + __uint_as_float((uint32_t)(acc2[r][b] >> 32));
                v += __shfl_xor_sync(0xffffffffu, v, 16);
                v += __shfl_xor_sync(0xffffffffu, v, 8);
                v += __shfl_xor_sync(0xffffffffu, v, 4);
                v += __shfl_xor_sync(0xffffffffu, v, 2);
                v += __shfl_xor_sync(0xffffffffu, v, 1);
                if (lane == 0)
                    g_part[kh][b * DOUT + row0 + idx[r]] = v;
            }
        }
    }
}

// ---------------------------------------------------------------------------
// Kernel 4: out = part0 + part1 + bias   (grid 86 x 128, float4)
// ---------------------------------------------------------------------------
__global__ __launch_bounds__(128) void k_add(
    const float* __restrict__ bias,
    float* __restrict__ out)
{
    const int e = blockIdx.x * 128 + threadIdx.x;      // [0, 11008) float4 units
    const float4 a = reinterpret_cast<const float4*>(g_part[0])[e];
    const float4 b = reinterpret_cast<const float4*>(g_part[1])[e];
    const int o4 = e % (DOUT / 4);
    const float4 bs = reinterpret_cast<const float4*>(bias)[o4];
    float4 o;
    o.x = a.x + b.x + bs.x;
    o.y = a.y + b.y + bs.y;
    o.z = a.z + b.z + bs.z;
    o.w = a.w + b.w + bs.w;
    reinterpret_cast<float4*>(out)[e] = o;
}

// ---------------------------------------------------------------------------
extern "C" void kernel_launch(void* const* d_in, const int* in_sizes, int n_in,
                              void* d_out, int out_size)
{
    const float* input  = (const float*)d_in[0];
    const float* weight = (const float*)d_in[1];
    const float* bias   = (const float*)d_in[2];
    const float* U      = (const float*)d_in[3];
    const float* S      = (const float*)d_in[4];
    const float* V      = (const float*)d_in[5];
    const float* scale  = (const float*)d_in[6];
    const float* thresh = (const float*)d_in[7];
    float* out = (float*)d_out;

    const int smem_bytes = (8192 + 1024 + 8 * DEPTH * 512) * (int)sizeof(float); // 102400
    cudaFuncSetAttribute(k_gemv, cudaFuncAttributeMaxDynamicSharedMemorySize, smem_bytes);

    k_mask_lr<<<NCHUNK, 128>>>(input, V, scale, thresh);
    k_lr_reduce<<<16, 256>>>(S);
    k_gemv<<<296, 256, smem_bytes>>>(weight, U);
    k_add<<<86, 128>>>(bias, out);
}

// round 15
// speedup vs baseline: 1.2639x; 1.1347x over previous
#include <cuda_runtime.h>
#include <cstdint>

// Problem constants (fixed by dataset)
#define BATCH   4
#define DIN     4096
#define DOUT    11008
#define RANK    512

// k1/k2 low-rank tiling
#define NCHUNK  256
#define CHUNK_D 16                 // d-rows per chunk

// k_gemv streaming
#define KT      128                // floats per stage per row
#define NSTAGE  (DIN / KT)         // 32 (full K, no split)
#define DEPTH   3                  // per-warp ring stages (2 groups in flight)
#define NSLOT   5                  // row slots per warp (stride-16)
#define SLOTF   (NSLOT * KT)       // 640 floats per ring stage per warp

// Scratch (allocation-free rule: __device__ globals)
__device__ float  g_xm[BATCH * DIN];            // masked input, SoA [b][d]
__device__ float4 g_lr_part[NCHUNK * 512];      // low-rank partials (2 MB)
__device__ float  g_lrs[BATCH * RANK];          // S-scaled lr, SoA [b][r]

// packed f32x2 FMA: acc.{lo,hi} += a.{lo,hi} * b.{lo,hi}
#define FMA2(acc, a, b) \
    asm volatile("fma.rn.f32x2 %0, %1, %2, %0;" : "+l"(acc) : "l"(a), "l"(b))

__device__ __forceinline__ void cp_async16(void* s, const void* g) {
    uint32_t sa = (uint32_t)__cvta_generic_to_shared(s);
    asm volatile("cp.async.cg.shared.global [%0], [%1], 16;\n" :: "r"(sa), "l"(g));
}
#define CP_COMMIT()  asm volatile("cp.async.commit_group;\n" ::: "memory")
#define CP_WAIT(n)   asm volatile("cp.async.wait_group %0;\n" :: "n"(n) : "memory")

// ---------------------------------------------------------------------------
// Kernel 1: mask split + per-chunk low-rank partial   (grid 256 x 128)
//   Partials stored coalesced in permuted layout: slot = c*512 + comp*128 + t.
// ---------------------------------------------------------------------------
__global__ __launch_bounds__(128) void k_mask_lr(
    const float* __restrict__ input,
    const float* __restrict__ V,
    const float* __restrict__ scale,
    const float* __restrict__ thr)
{
    __shared__ float4 sxc[CHUNK_D];

    const int c = blockIdx.x;
    const int t = threadIdx.x;

    if (t < CHUNK_D) {
        const int d = c * CHUNK_D + t;
        const float th = thr[0];
        const float sc = scale[d];
        float x0 = input[0 * DIN + d];
        float x1 = input[1 * DIN + d];
        float x2 = input[2 * DIN + d];
        float x3 = input[3 * DIN + d];
        bool m0 = fabsf(x0 * sc) > th;
        bool m1 = fabsf(x1 * sc) > th;
        bool m2 = fabsf(x2 * sc) > th;
        bool m3 = fabsf(x3 * sc) > th;
        g_xm[0 * DIN + d] = m0 ? x0 : 0.0f;
        g_xm[1 * DIN + d] = m1 ? x1 : 0.0f;
        g_xm[2 * DIN + d] = m2 ? x2 : 0.0f;
        g_xm[3 * DIN + d] = m3 ? x3 : 0.0f;
        float4 xc;
        xc.x = m0 ? 0.0f : x0;
        xc.y = m1 ? 0.0f : x1;
        xc.z = m2 ? 0.0f : x2;
        xc.w = m3 ? 0.0f : x3;
        sxc[t] = xc;
    }
    __syncthreads();

    const float4* __restrict__ V4 = reinterpret_cast<const float4*>(V);

    float4 v[CHUNK_D];                       // 16 LDG.128 in flight
#pragma unroll
    for (int j = 0; j < CHUNK_D; j++)
        v[j] = V4[(size_t)(c * CHUNK_D + j) * (RANK / 4) + t];

    float4 a0 = make_float4(0.f, 0.f, 0.f, 0.f);
    float4 a1 = a0, a2 = a0, a3 = a0;
#pragma unroll
    for (int j = 0; j < CHUNK_D; j++) {
        const float4 xb = sxc[j];
        a0.x += v[j].x * xb.x; a0.y += v[j].x * xb.y; a0.z += v[j].x * xb.z; a0.w += v[j].x * xb.w;
        a1.x += v[j].y * xb.x; a1.y += v[j].y * xb.y; a1.z += v[j].y * xb.z; a1.w += v[j].y * xb.w;
        a2.x += v[j].z * xb.x; a2.y += v[j].z * xb.y; a2.z += v[j].z * xb.z; a2.w += v[j].z * xb.w;
        a3.x += v[j].w * xb.x; a3.y += v[j].w * xb.y; a3.z += v[j].w * xb.z; a3.w += v[j].w * xb.w;
    }

    float4* outp = g_lr_part + (size_t)c * 512;   // coalesced stores (permuted r)
    outp[0 * 128 + t] = a0;
    outp[1 * 128 + t] = a1;
    outp[2 * 128 + t] = a2;
    outp[3 * 128 + t] = a3;
}

// ---------------------------------------------------------------------------
// Kernel 2: reduce partials over 256 chunks, fold S   (grid 16 x 256)
//   Element e (permuted r): r = 4*(e&127) + (e>>7).
// ---------------------------------------------------------------------------
__global__ __launch_bounds__(256) void k_lr_reduce(const float* __restrict__ S)
{
    __shared__ float4 sred[256];

    const int tid   = threadIdx.x;
    const int eloc  = tid & 31;
    const int clane = tid >> 5;                 // chunk lane [0,8)
    const int e     = blockIdx.x * 32 + eloc;

    float4 acc = make_float4(0.f, 0.f, 0.f, 0.f);
#pragma unroll 8
    for (int j = 0; j < NCHUNK / 8; j++) {
        float4 p = g_lr_part[(size_t)(clane + 8 * j) * 512 + e];  // coalesced over e
        acc.x += p.x; acc.y += p.y; acc.z += p.z; acc.w += p.w;
    }
    sred[tid] = acc;
    __syncthreads();

    if (tid < 32) {
        float4 a = sred[tid];
#pragma unroll
        for (int l = 1; l < 8; l++) {
            float4 p = sred[tid + 32 * l];
            a.x += p.x; a.y += p.y; a.z += p.z; a.w += p.w;
        }
        const int ee = blockIdx.x * 32 + tid;
        const int r  = 4 * (ee & 127) + (ee >> 7);
        const float s = S[r];
        g_lrs[0 * RANK + r] = a.x * s;
        g_lrs[1 * RANK + r] = a.y * s;
        g_lrs[2 * RANK + r] = a.z * s;
        g_lrs[3 * RANK + r] = a.w * s;
    }
}

// ---------------------------------------------------------------------------
// Kernel 3: full-K streaming GEMV, direct output (no K-split, no k_add).
//   grid 148 (one CTA per row-range, single wave), 512 thr = 16 warps.
//   Warp w owns rows  idx = w + 16*r, r in [0,5)  -> 5 rows for warps < 11,
//   4 rows otherwise: near-perfect byte balance, ONE pipeline, one prologue.
//   Per-warp cp.async ring: DEPTH 3 stages x 5 rows x 128 floats; mainloop
//   is barrier-free (per-warp commits/waits only).
// ---------------------------------------------------------------------------
__global__ __launch_bounds__(512, 1) void k_gemv(
    const float* __restrict__ W,
    const float* __restrict__ U,
    const float* __restrict__ bias,
    float* __restrict__ out)
{
    extern __shared__ float smem[];
    float* sx   = smem;             // 16384 floats: x SoA [b][4096] (64 KB)
    float* slr  = smem + 16384;     // 2048 floats:  lr SoA [b][512]  (8 KB)
    float* ring = smem + 18432;     // 16 warps * DEPTH * 640 floats (120 KB)

    const int tid  = threadIdx.x;
    const int wid  = tid >> 5;
    const int lane = tid & 31;
    const int bid  = blockIdx.x;
    const int row0  = 74 * bid + (bid < 56 ? bid : 56);
    const int nrows = (bid < 56) ? 75 : 74;

    // ---- fill x + lr via cp.async (linear SoA copies) ----
    {
        const float4* gx4 = reinterpret_cast<const float4*>(g_xm);
        float4*       sx4 = reinterpret_cast<float4*>(sx);
#pragma unroll
        for (int i = 0; i < 8; i++) {
            const int i2 = tid + 512 * i;          // [0,4096)
            cp_async16(&sx4[i2], &gx4[i2]);
        }
        const float4* gl4 = reinterpret_cast<const float4*>(g_lrs);
        float4*       sl4 = reinterpret_cast<float4*>(slr);
        {
            cp_async16(&sl4[tid], &gl4[tid]);      // 512 float4
        }
        CP_COMMIT();
        CP_WAIT(0);
    }
    __syncthreads();

    float* wring = ring + wid * (DEPTH * SLOTF);

    // stride-16 row slots for this warp
    int  idx[NSLOT]; bool valid[NSLOT]; const float* wp[NSLOT];
#pragma unroll
    for (int r = 0; r < NSLOT; r++) {
        idx[r]   = wid + 16 * r;
        valid[r] = idx[r] < nrows;
        wp[r]    = W + (size_t)(row0 + idx[r]) * DIN;
    }

    // prologue: stages 0..DEPTH-2
#pragma unroll
    for (int s = 0; s < DEPTH - 1; s++) {
#pragma unroll
        for (int r = 0; r < NSLOT; r++)
            if (valid[r])
                cp_async16(wring + (s % DEPTH) * SLOTF + r * KT + lane * 4,
                           wp[r] + s * KT + lane * 4);
        CP_COMMIT();
    }

    unsigned long long acc2[NSLOT][4];
#pragma unroll
    for (int r = 0; r < NSLOT; r++)
#pragma unroll
        for (int b = 0; b < 4; b++) acc2[r][b] = 0ULL;

    // mainloop: 32 continuous stages; always-commit keeps wait uniform
#pragma unroll 4
    for (int s = 0; s < NSTAGE; s++) {
        const int tnext = s + (DEPTH - 1);
        if (tnext < NSTAGE) {
#pragma unroll
            for (int r = 0; r < NSLOT; r++)
                if (valid[r])
                    cp_async16(wring + (tnext % DEPTH) * SLOTF + r * KT + lane * 4,
                               wp[r] + tnext * KT + lane * 4);
        }
        CP_COMMIT();
        CP_WAIT(DEPTH - 1);

        const float* buf = wring + (s % DEPTH) * SLOTF;
        ulonglong2 xv[4];
#pragma unroll
        for (int b = 0; b < 4; b++)
            xv[b] = *reinterpret_cast<const ulonglong2*>(sx + b * DIN + s * KT + lane * 4);
#pragma unroll
        for (int r = 0; r < NSLOT; r++) {
            const ulonglong2 wv = *reinterpret_cast<const ulonglong2*>(buf + r * KT + lane * 4);
#pragma unroll
            for (int b = 0; b < 4; b++) {
                FMA2(acc2[r][b], wv.x, xv[b].x);
                FMA2(acc2[r][b], wv.y, xv[b].y);
            }
        }
    }

    // U epilogue: full RANK
#pragma unroll
    for (int r = 0; r < NSLOT; r++) {
        if (!valid[r]) continue;
        const float* up = U + (size_t)(row0 + idx[r]) * RANK;
#pragma unroll
        for (int q = 0; q < 4; q++) {
            const ulonglong2 uv = *reinterpret_cast<const ulonglong2*>(up + q * 128 + lane * 4);
#pragma unroll
            for (int b = 0; b < 4; b++) {
                const ulonglong2 lv =
                    *reinterpret_cast<const ulonglong2*>(slr + b * RANK + q * 128 + lane * 4);
                FMA2(acc2[r][b], uv.x, lv.x);
                FMA2(acc2[r][b], uv.y, lv.y);
            }
        }
    }

    // fold packed halves, warp-reduce, write output + bias directly
#pragma unroll
    for (int r = 0; r < NSLOT; r++) {
        if (!valid[r]) continue;
        const int grow = row0 + idx[r];
#pragma unroll
        for (int b = 0; b < 4; b++) {
            float v = __uint_as_float((uint32_t)acc2[r][b])
                    + __uint_as_float((uint32_t)(acc2[r][b] >> 32));
            v += __shfl_xor_sync(0xffffffffu, v, 16);
            v += __shfl_xor_sync(0xffffffffu, v, 8);
            v += __shfl_xor_sync(0xffffffffu, v, 4);
            v += __shfl_xor_sync(0xffffffffu, v, 2);
            v += __shfl_xor_sync(0xffffffffu, v, 1);
            if (lane == 0)
                out[(size_t)b * DOUT + grow] = v + bias[grow];
        }
    }
}

// ---------------------------------------------------------------------------
extern "C" void kernel_launch(void* const* d_in, const int* in_sizes, int n_in,
                              void* d_out, int out_size)
{
    const float* input  = (const float*)d_in[0];
    const float* weight = (const float*)d_in[1];
    const float* bias   = (const float*)d_in[2];
    const float* U      = (const float*)d_in[3];
    const float* S      = (const float*)d_in[4];
    const float* V      = (const float*)d_in[5];
    const float* scale  = (const float*)d_in[6];
    const float* thresh = (const float*)d_in[7];
    float* out = (float*)d_out;

    const int smem_bytes = (16384 + 2048 + 16 * DEPTH * SLOTF) * (int)sizeof(float); // 196608
    cudaFuncSetAttribute(k_gemv, cudaFuncAttributeMaxDynamicSharedMemorySize, smem_bytes);

    k_mask_lr<<<NCHUNK, 128>>>(input, V, scale, thresh);
    k_lr_reduce<<<16, 256>>>(S);
    k_gemv<<<148, 512, smem_bytes>>>(weight, U, bias, out);
}